// round 7
// baseline (speedup 1.0000x reference)
#include <cuda_runtime.h>
#include <cuda_fp16.h>
#include <cstdint>

#define MAXN 100000
#define MAXE 1600000
#define CAP  96          // max in-degree bucket capacity (Poisson(16) tail << 1e-30)

// ---------------- device scratch (no allocation allowed) -------------------
__device__ int    g_cnt[MAXN];
__device__ int    g_csr[MAXN * CAP];                  // bucketed CSR (38.4 MB)
__device__ __align__(16) __half g_h1h  [MAXN * 128];  // dinv * (x @ W1)   (fp16)
__device__ __align__(16) __half g_act1h[MAXN * 128];  // relu layer-1 out  (fp16)
__device__ __align__(16) __half g_h2h  [MAXN * 64];   // dinv * (act1@W2)  (fp16)

// ---------------------------------------------------------------------------
__global__ void zero_cnt_kernel(int n) {
    int i = blockIdx.x * blockDim.x + threadIdx.x;
    if (i < n) g_cnt[i] = 0;
}

// single-pass CSR: count + scatter in one atomic
__global__ void fill_kernel(const int* __restrict__ src,
                            const int* __restrict__ dst, int e) {
    int i = blockIdx.x * blockDim.x + threadIdx.x;
    if (i < e) {
        int d = dst[i];
        int slot = atomicAdd(&g_cnt[d], 1);
        if (slot < CAP) g_csr[d * CAP + slot] = src[i];
    }
}

// ---------------------------------------------------------------------------
// fp16 tensor-core GEMM: C[M,BN] = half( dinv[row] * (A[M,128] @ B[128,BN]) )
__device__ __forceinline__ void mma_f16(float c[4], const uint32_t a[4],
                                        uint32_t b0, uint32_t b1) {
    asm volatile(
        "mma.sync.aligned.m16n8k16.row.col.f32.f16.f16.f32 "
        "{%0,%1,%2,%3}, {%4,%5,%6,%7}, {%8,%9}, {%0,%1,%2,%3};"
        : "+f"(c[0]), "+f"(c[1]), "+f"(c[2]), "+f"(c[3])
        : "r"(a[0]), "r"(a[1]), "r"(a[2]), "r"(a[3]), "r"(b0), "r"(b1));
}

// 256 threads, 128-row tiles, BK=64 (2 chunks), warp tile (MT*16) x 64.
template<int BN, int MT, int WARPS_N, typename AT>
__device__ __forceinline__ void hgemm_body(
    const AT* __restrict__ A, const float* __restrict__ B,
    __half* __restrict__ C, int M)
{
    constexpr int NT = 8;
    constexpr int ST = 72;                 // smem stride (halves), pad 8
    __shared__ alignas(16) __half As[128 * ST];
    __shared__ alignas(16) __half Bs[BN * ST];

    const int tid  = threadIdx.x;
    const int wid  = tid >> 5;
    const int lane = tid & 31;
    const int lg   = lane >> 2;
    const int lt   = lane & 3;
    const int wn   = (wid % WARPS_N) * 64;
    const int wm   = (wid / WARPS_N) * (MT * 16);
    const int row0 = blockIdx.x * 128;

    float c[MT][NT][4];
#pragma unroll
    for (int mt = 0; mt < MT; mt++)
#pragma unroll
        for (int nt = 0; nt < NT; nt++)
#pragma unroll
            for (int q = 0; q < 4; q++) c[mt][nt][q] = 0.0f;

    for (int k0 = 0; k0 < 128; k0 += 64) {
        // ---- A tile: 128 rows x 64 k -> As[r][k] halves
#pragma unroll
        for (int it = 0; it < 8; it++) {
            int slot = tid + it * 256;        // 2048 groups of 4 halves
            int r  = slot >> 4;
            int k4 = slot & 15;
            if constexpr (sizeof(AT) == 4) {  // fp32 source
                float4 v = make_float4(0.f, 0.f, 0.f, 0.f);
                if (row0 + r < M)
                    v = *(const float4*)&A[(long)(row0 + r) * 128 + k0 + k4 * 4];
                *(__half2*)&As[r * ST + k4 * 4]     = __floats2half2_rn(v.x, v.y);
                *(__half2*)&As[r * ST + k4 * 4 + 2] = __floats2half2_rn(v.z, v.w);
            } else {                          // fp16 source: straight copy
                uint2 v = make_uint2(0u, 0u);
                if (row0 + r < M)
                    v = *(const uint2*)&A[(long)(row0 + r) * 128 + k0 + k4 * 4];
                *(uint2*)&As[r * ST + k4 * 4] = v;
            }
        }
        // ---- B tile: 64 k x BN fp32 -> transposed Bs[n][k] halves.
        // Lane-fast dim = k2 (pair of k rows) -> conflict-free half2 stores.
        constexpr int BSLOTS = 32 * (BN / 4) / 256;   // 4 (BN=128) or 2 (BN=64)
#pragma unroll
        for (int it = 0; it < BSLOTS; it++) {
            int slot = tid + it * 256;
            int k2 = slot & 31;               // 0..31  (k pair index)
            int n4 = slot >> 5;               // 0..BN/4-1
            float4 va = *(const float4*)&B[(long)(k0 + 2 * k2)     * BN + n4 * 4];
            float4 vb = *(const float4*)&B[(long)(k0 + 2 * k2 + 1) * BN + n4 * 4];
            *(__half2*)&Bs[(n4 * 4 + 0) * ST + 2 * k2] = __floats2half2_rn(va.x, vb.x);
            *(__half2*)&Bs[(n4 * 4 + 1) * ST + 2 * k2] = __floats2half2_rn(va.y, vb.y);
            *(__half2*)&Bs[(n4 * 4 + 2) * ST + 2 * k2] = __floats2half2_rn(va.z, vb.z);
            *(__half2*)&Bs[(n4 * 4 + 3) * ST + 2 * k2] = __floats2half2_rn(va.w, vb.w);
        }
        __syncthreads();

#pragma unroll
        for (int ks = 0; ks < 4; ks++) {
            int kk = ks * 16;
            uint32_t a[MT][4];
#pragma unroll
            for (int mt = 0; mt < MT; mt++) {
                int rr = wm + mt * 16 + lg;
                a[mt][0] = *(const uint32_t*)&As[rr * ST + kk + 2 * lt];
                a[mt][1] = *(const uint32_t*)&As[(rr + 8) * ST + kk + 2 * lt];
                a[mt][2] = *(const uint32_t*)&As[rr * ST + kk + 2 * lt + 8];
                a[mt][3] = *(const uint32_t*)&As[(rr + 8) * ST + kk + 2 * lt + 8];
            }
#pragma unroll
            for (int nt = 0; nt < NT; nt++) {
                int nn = wn + nt * 8 + lg;
                uint32_t b0 = *(const uint32_t*)&Bs[nn * ST + kk + 2 * lt];
                uint32_t b1 = *(const uint32_t*)&Bs[nn * ST + kk + 2 * lt + 8];
#pragma unroll
                for (int mt = 0; mt < MT; mt++)
                    mma_f16(c[mt][nt], a[mt], b0, b1);
            }
        }
        __syncthreads();
    }

    // epilogue: scale by dinv[row] = rsqrt(cnt+1), convert to half, store
#pragma unroll
    for (int mt = 0; mt < MT; mt++) {
        int r0 = row0 + wm + mt * 16 + lg;
        int r1 = r0 + 8;
        float s0 = (r0 < M) ? rsqrtf((float)(__ldg(&g_cnt[r0]) + 1)) : 0.f;
        float s1 = (r1 < M) ? rsqrtf((float)(__ldg(&g_cnt[r1]) + 1)) : 0.f;
#pragma unroll
        for (int nt = 0; nt < NT; nt++) {
            int col = wn + nt * 8 + lt * 2;
            if (r0 < M)
                *(__half2*)&C[(long)r0 * BN + col] =
                    __floats2half2_rn(c[mt][nt][0] * s0, c[mt][nt][1] * s0);
            if (r1 < M)
                *(__half2*)&C[(long)r1 * BN + col] =
                    __floats2half2_rn(c[mt][nt][2] * s1, c[mt][nt][3] * s1);
        }
    }
}

__global__ void __launch_bounds__(256) gemm1_kernel(
    const float* __restrict__ A, const float* __restrict__ B, int M) {
    hgemm_body<128, 2, 2>(A, B, g_h1h, M);      // 8 warps: 4m x 2n
}
__global__ void __launch_bounds__(256) gemm2_kernel(
    const float* __restrict__ B, int M) {
    hgemm_body<64, 1, 1>(g_act1h, B, g_h2h, M); // 8 warps: 8m x 1n
}

// ---------------------------------------------------------------------------
// Layer-1 pull: act1 = relu( dinv[d] * (sum_s h1'[s] + h1'[d]) + b1 )
// (h1' already premultiplied by dinv[src] in the gemm1 epilogue)
__global__ void agg1_kernel(const float* __restrict__ b1, int n) {
    int w    = (blockIdx.x * blockDim.x + threadIdx.x) >> 5;
    int lane = threadIdx.x & 31;
    if (w >= n) return;

    int cntt = g_cnt[w];
    int cnt  = cntt < CAP ? cntt : CAP;
    int base = w * CAP;
    const uint2* hp = (const uint2*)g_h1h;   // 4 halves per lane

    float a0 = 0.f, a1 = 0.f, a2 = 0.f, a3 = 0.f;
    int j = 0;
    for (; j + 4 <= cnt; j += 4) {
        int s0 = g_csr[base + j];
        int s1 = g_csr[base + j + 1];
        int s2 = g_csr[base + j + 2];
        int s3 = g_csr[base + j + 3];
        uint2 u0 = hp[s0 * 32 + lane];
        uint2 u1 = hp[s1 * 32 + lane];
        uint2 u2 = hp[s2 * 32 + lane];
        uint2 u3 = hp[s3 * 32 + lane];
        float2 p, q;
        p = __half22float2(*(__half2*)&u0.x); q = __half22float2(*(__half2*)&u0.y);
        a0 += p.x; a1 += p.y; a2 += q.x; a3 += q.y;
        p = __half22float2(*(__half2*)&u1.x); q = __half22float2(*(__half2*)&u1.y);
        a0 += p.x; a1 += p.y; a2 += q.x; a3 += q.y;
        p = __half22float2(*(__half2*)&u2.x); q = __half22float2(*(__half2*)&u2.y);
        a0 += p.x; a1 += p.y; a2 += q.x; a3 += q.y;
        p = __half22float2(*(__half2*)&u3.x); q = __half22float2(*(__half2*)&u3.y);
        a0 += p.x; a1 += p.y; a2 += q.x; a3 += q.y;
    }
    for (; j < cnt; j++) {
        int s = g_csr[base + j];
        uint2 u = hp[s * 32 + lane];
        float2 p = __half22float2(*(__half2*)&u.x);
        float2 q = __half22float2(*(__half2*)&u.y);
        a0 += p.x; a1 += p.y; a2 += q.x; a3 += q.y;
    }

    uint2 us = hp[w * 32 + lane];
    float dw = rsqrtf((float)(cntt + 1));
    float2 ps = __half22float2(*(__half2*)&us.x);
    float2 qs = __half22float2(*(__half2*)&us.y);
    float4 bb = ((const float4*)b1)[lane];
    float r0 = fmaxf(fmaf(dw, a0 + ps.x, bb.x), 0.f);
    float r1 = fmaxf(fmaf(dw, a1 + ps.y, bb.y), 0.f);
    float r2 = fmaxf(fmaf(dw, a2 + qs.x, bb.z), 0.f);
    float r3 = fmaxf(fmaf(dw, a3 + qs.y, bb.w), 0.f);

    __half2* op = (__half2*)&g_act1h[w * 128 + lane * 4];
    op[0] = __floats2half2_rn(r0, r1);
    op[1] = __floats2half2_rn(r2, r3);
}

// Layer-2 pull + bias + log_softmax. Warp per node, 2 cols per lane.
__global__ void agg2_kernel(const float* __restrict__ b2,
                            float* __restrict__ out, int n) {
    int w    = (blockIdx.x * blockDim.x + threadIdx.x) >> 5;
    int lane = threadIdx.x & 31;
    if (w >= n) return;

    int cntt = g_cnt[w];
    int cnt  = cntt < CAP ? cntt : CAP;
    int base = w * CAP;
    const uint32_t* hp = (const uint32_t*)g_h2h;  // half2 per lane

    float ax = 0.f, ay = 0.f;
    int j = 0;
    for (; j + 4 <= cnt; j += 4) {
        int s0 = g_csr[base + j];
        int s1 = g_csr[base + j + 1];
        int s2 = g_csr[base + j + 2];
        int s3 = g_csr[base + j + 3];
        uint32_t u0 = hp[s0 * 32 + lane];
        uint32_t u1 = hp[s1 * 32 + lane];
        uint32_t u2 = hp[s2 * 32 + lane];
        uint32_t u3 = hp[s3 * 32 + lane];
        float2 f;
        f = __half22float2(*(__half2*)&u0); ax += f.x; ay += f.y;
        f = __half22float2(*(__half2*)&u1); ax += f.x; ay += f.y;
        f = __half22float2(*(__half2*)&u2); ax += f.x; ay += f.y;
        f = __half22float2(*(__half2*)&u3); ax += f.x; ay += f.y;
    }
    for (; j < cnt; j++) {
        int s = g_csr[base + j];
        uint32_t u = hp[s * 32 + lane];
        float2 f = __half22float2(*(__half2*)&u);
        ax += f.x; ay += f.y;
    }

    uint32_t usv = hp[w * 32 + lane];
    float dw = rsqrtf((float)(cntt + 1));
    float2 fs = __half22float2(*(__half2*)&usv);
    float2 bb = ((const float2*)b2)[lane];
    float ox = fmaf(dw, ax + fs.x, bb.x);
    float oy = fmaf(dw, ay + fs.y, bb.y);

    float m = fmaxf(ox, oy);
#pragma unroll
    for (int o = 16; o; o >>= 1) m = fmaxf(m, __shfl_xor_sync(0xFFFFFFFFu, m, o));
    float s = __expf(ox - m) + __expf(oy - m);
#pragma unroll
    for (int o = 16; o; o >>= 1) s += __shfl_xor_sync(0xFFFFFFFFu, s, o);
    float lse = m + __logf(s);

    ((float2*)out)[w * 32 + lane] = make_float2(ox - lse, oy - lse);
}

// ---------------------------------------------------------------------------
extern "C" void kernel_launch(void* const* d_in, const int* in_sizes, int n_in,
                              void* d_out, int out_size) {
    const float* x  = (const float*)d_in[0];
    const int*   ei = (const int*)  d_in[1];
    const float* W1 = (const float*)d_in[2];
    const float* b1 = (const float*)d_in[3];
    const float* W2 = (const float*)d_in[4];
    const float* b2 = (const float*)d_in[5];
    float* out = (float*)d_out;

    const int n = in_sizes[0] / 128;
    const int e = in_sizes[1] / 2;
    const int* src = ei;
    const int* dst = ei + e;

    zero_cnt_kernel<<<(n + 255) / 256, 256>>>(n);
    fill_kernel    <<<(e + 255) / 256, 256>>>(src, dst, e);

    gemm1_kernel<<<(n + 127) / 128, 256>>>(x, W1, n);
    agg1_kernel <<<(n * 32 + 255) / 256, 256>>>(b1, n);
    gemm2_kernel<<<(n + 127) / 128, 256>>>(W2, n);
    agg2_kernel <<<(n * 32 + 255) / 256, 256>>>(b2, out, n);
}

// round 8
// speedup vs baseline: 1.0393x; 1.0393x over previous
#include <cuda_runtime.h>
#include <cuda_fp16.h>
#include <cstdint>

#define MAXN 100000
#define MAXE 1600000
#define CAP  96          // max in-degree bucket capacity (Poisson(16) tail << 1e-30)

// ---------------- device scratch (no allocation allowed) -------------------
__device__ int    g_cnt[MAXN];
__device__ int    g_csr[MAXN * CAP];                  // bucketed CSR (38.4 MB)
__device__ __align__(16) __half g_h1h  [MAXN * 128];  // dinv * (x @ W1)   (fp16)
__device__ __align__(16) __half g_act1h[MAXN * 128];  // relu layer-1 out  (fp16)
__device__ __align__(16) __half g_h2h  [MAXN * 64];   // dinv * (act1@W2)  (fp16)

// ---------------------------------------------------------------------------
__global__ void zero_cnt_kernel(int n) {
    int i = blockIdx.x * blockDim.x + threadIdx.x;
    if (i < n) g_cnt[i] = 0;
}

// single-pass CSR: count + scatter in one atomic
__global__ void fill_kernel(const int* __restrict__ src,
                            const int* __restrict__ dst, int e) {
    int i = blockIdx.x * blockDim.x + threadIdx.x;
    if (i < e) {
        int d = dst[i];
        int slot = atomicAdd(&g_cnt[d], 1);
        if (slot < CAP) g_csr[d * CAP + slot] = src[i];
    }
}

// ---------------------------------------------------------------------------
// fp16 tensor-core GEMM: C[M,BN] = half( dinv[row] * (A[M,128] @ B[128,BN]) )
__device__ __forceinline__ void mma_f16(float c[4], const uint32_t a[4],
                                        uint32_t b0, uint32_t b1) {
    asm volatile(
        "mma.sync.aligned.m16n8k16.row.col.f32.f16.f16.f32 "
        "{%0,%1,%2,%3}, {%4,%5,%6,%7}, {%8,%9}, {%0,%1,%2,%3};"
        : "+f"(c[0]), "+f"(c[1]), "+f"(c[2]), "+f"(c[3])
        : "r"(a[0]), "r"(a[1]), "r"(a[2]), "r"(a[3]), "r"(b0), "r"(b1));
}

// 256 threads, 128-row tiles, BK=64 (2 chunks), warp tile (MT*16) x 64.
template<int BN, int MT, int WARPS_N, typename AT>
__device__ __forceinline__ void hgemm_body(
    const AT* __restrict__ A, const float* __restrict__ B,
    __half* __restrict__ C, int M)
{
    constexpr int NT = 8;
    constexpr int ST = 72;                 // smem stride (halves), pad 8
    __shared__ alignas(16) __half As[128 * ST];
    __shared__ alignas(16) __half Bs[BN * ST];

    const int tid  = threadIdx.x;
    const int wid  = tid >> 5;
    const int lane = tid & 31;
    const int lg   = lane >> 2;
    const int lt   = lane & 3;
    const int wn   = (wid % WARPS_N) * 64;
    const int wm   = (wid / WARPS_N) * (MT * 16);
    const int row0 = blockIdx.x * 128;

    float c[MT][NT][4];
#pragma unroll
    for (int mt = 0; mt < MT; mt++)
#pragma unroll
        for (int nt = 0; nt < NT; nt++)
#pragma unroll
            for (int q = 0; q < 4; q++) c[mt][nt][q] = 0.0f;

    for (int k0 = 0; k0 < 128; k0 += 64) {
        // ---- A tile: 128 rows x 64 k -> As[r][k] halves
#pragma unroll
        for (int it = 0; it < 8; it++) {
            int slot = tid + it * 256;        // 2048 groups of 4 halves
            int r  = slot >> 4;
            int k4 = slot & 15;
            if constexpr (sizeof(AT) == 4) {  // fp32 source
                float4 v = make_float4(0.f, 0.f, 0.f, 0.f);
                if (row0 + r < M)
                    v = *(const float4*)&A[(long)(row0 + r) * 128 + k0 + k4 * 4];
                *(__half2*)&As[r * ST + k4 * 4]     = __floats2half2_rn(v.x, v.y);
                *(__half2*)&As[r * ST + k4 * 4 + 2] = __floats2half2_rn(v.z, v.w);
            } else {                          // fp16 source: straight copy
                uint2 v = make_uint2(0u, 0u);
                if (row0 + r < M)
                    v = *(const uint2*)&A[(long)(row0 + r) * 128 + k0 + k4 * 4];
                *(uint2*)&As[r * ST + k4 * 4] = v;
            }
        }
        // ---- B tile: 64 k x BN fp32 -> transposed Bs[n][k] halves.
        // Lane-fast dim = k2 (pair of k rows) -> conflict-free half2 stores.
        constexpr int BSLOTS = 32 * (BN / 4) / 256;   // 4 (BN=128) or 2 (BN=64)
#pragma unroll
        for (int it = 0; it < BSLOTS; it++) {
            int slot = tid + it * 256;
            int k2 = slot & 31;               // 0..31  (k pair index)
            int n4 = slot >> 5;               // 0..BN/4-1
            float4 va = *(const float4*)&B[(long)(k0 + 2 * k2)     * BN + n4 * 4];
            float4 vb = *(const float4*)&B[(long)(k0 + 2 * k2 + 1) * BN + n4 * 4];
            *(__half2*)&Bs[(n4 * 4 + 0) * ST + 2 * k2] = __floats2half2_rn(va.x, vb.x);
            *(__half2*)&Bs[(n4 * 4 + 1) * ST + 2 * k2] = __floats2half2_rn(va.y, vb.y);
            *(__half2*)&Bs[(n4 * 4 + 2) * ST + 2 * k2] = __floats2half2_rn(va.z, vb.z);
            *(__half2*)&Bs[(n4 * 4 + 3) * ST + 2 * k2] = __floats2half2_rn(va.w, vb.w);
        }
        __syncthreads();

#pragma unroll
        for (int ks = 0; ks < 4; ks++) {
            int kk = ks * 16;
            uint32_t a[MT][4];
#pragma unroll
            for (int mt = 0; mt < MT; mt++) {
                int rr = wm + mt * 16 + lg;
                a[mt][0] = *(const uint32_t*)&As[rr * ST + kk + 2 * lt];
                a[mt][1] = *(const uint32_t*)&As[(rr + 8) * ST + kk + 2 * lt];
                a[mt][2] = *(const uint32_t*)&As[rr * ST + kk + 2 * lt + 8];
                a[mt][3] = *(const uint32_t*)&As[(rr + 8) * ST + kk + 2 * lt + 8];
            }
#pragma unroll
            for (int nt = 0; nt < NT; nt++) {
                int nn = wn + nt * 8 + lg;
                uint32_t b0 = *(const uint32_t*)&Bs[nn * ST + kk + 2 * lt];
                uint32_t b1 = *(const uint32_t*)&Bs[nn * ST + kk + 2 * lt + 8];
#pragma unroll
                for (int mt = 0; mt < MT; mt++)
                    mma_f16(c[mt][nt], a[mt], b0, b1);
            }
        }
        __syncthreads();
    }

    // epilogue: scale by dinv[row] = rsqrt(cnt+1), convert to half, store
#pragma unroll
    for (int mt = 0; mt < MT; mt++) {
        int r0 = row0 + wm + mt * 16 + lg;
        int r1 = r0 + 8;
        float s0 = (r0 < M) ? rsqrtf((float)(__ldg(&g_cnt[r0]) + 1)) : 0.f;
        float s1 = (r1 < M) ? rsqrtf((float)(__ldg(&g_cnt[r1]) + 1)) : 0.f;
#pragma unroll
        for (int nt = 0; nt < NT; nt++) {
            int col = wn + nt * 8 + lt * 2;
            if (r0 < M)
                *(__half2*)&C[(long)r0 * BN + col] =
                    __floats2half2_rn(c[mt][nt][0] * s0, c[mt][nt][1] * s0);
            if (r1 < M)
                *(__half2*)&C[(long)r1 * BN + col] =
                    __floats2half2_rn(c[mt][nt][2] * s1, c[mt][nt][3] * s1);
        }
    }
}

__global__ void __launch_bounds__(256) gemm1_kernel(
    const float* __restrict__ A, const float* __restrict__ B, int M) {
    hgemm_body<128, 2, 2>(A, B, g_h1h, M);      // 8 warps: 4m x 2n
}
__global__ void __launch_bounds__(256) gemm2_kernel(
    const float* __restrict__ B, int M) {
    hgemm_body<64, 1, 1>(g_act1h, B, g_h2h, M); // 8 warps: 8m x 1n
}

// ---------------------------------------------------------------------------
// Layer-1 pull: act1 = relu( dinv[d] * (sum_s h1'[s] + h1'[d]) + b1 )
// Hot loop: fp16 HADD2 tree over 8 edges, single convert, fp32 accumulate.
__global__ void agg1_kernel(const float* __restrict__ b1, int n) {
    int w    = (blockIdx.x * blockDim.x + threadIdx.x) >> 5;
    int lane = threadIdx.x & 31;
    if (w >= n) return;

    int cntt = g_cnt[w];
    int cnt  = cntt < CAP ? cntt : CAP;
    int base = w * CAP;
    const __half2* hp = (const __half2*)g_h1h;   // 2 half2 per lane per row
    const int li = lane * 2;

    float a0 = 0.f, a1 = 0.f, a2 = 0.f, a3 = 0.f;
    int j = 0;
    for (; j + 8 <= cnt; j += 8) {
        int s0 = g_csr[base + j + 0] * 64 + li;
        int s1 = g_csr[base + j + 1] * 64 + li;
        int s2 = g_csr[base + j + 2] * 64 + li;
        int s3 = g_csr[base + j + 3] * 64 + li;
        int s4 = g_csr[base + j + 4] * 64 + li;
        int s5 = g_csr[base + j + 5] * 64 + li;
        int s6 = g_csr[base + j + 6] * 64 + li;
        int s7 = g_csr[base + j + 7] * 64 + li;
        __half2 x0 = hp[s0],     y0 = hp[s0 + 1];
        __half2 x1 = hp[s1],     y1 = hp[s1 + 1];
        __half2 x2 = hp[s2],     y2 = hp[s2 + 1];
        __half2 x3 = hp[s3],     y3 = hp[s3 + 1];
        __half2 x4 = hp[s4],     y4 = hp[s4 + 1];
        __half2 x5 = hp[s5],     y5 = hp[s5 + 1];
        __half2 x6 = hp[s6],     y6 = hp[s6 + 1];
        __half2 x7 = hp[s7],     y7 = hp[s7 + 1];
        __half2 sx = __hadd2(__hadd2(__hadd2(x0, x1), __hadd2(x2, x3)),
                             __hadd2(__hadd2(x4, x5), __hadd2(x6, x7)));
        __half2 sy = __hadd2(__hadd2(__hadd2(y0, y1), __hadd2(y2, y3)),
                             __hadd2(__hadd2(y4, y5), __hadd2(y6, y7)));
        float2 fx = __half22float2(sx);
        float2 fy = __half22float2(sy);
        a0 += fx.x; a1 += fx.y; a2 += fy.x; a3 += fy.y;
    }
    for (; j + 4 <= cnt; j += 4) {
        int s0 = g_csr[base + j + 0] * 64 + li;
        int s1 = g_csr[base + j + 1] * 64 + li;
        int s2 = g_csr[base + j + 2] * 64 + li;
        int s3 = g_csr[base + j + 3] * 64 + li;
        __half2 sx = __hadd2(__hadd2(hp[s0],     hp[s1]),     __hadd2(hp[s2],     hp[s3]));
        __half2 sy = __hadd2(__hadd2(hp[s0 + 1], hp[s1 + 1]), __hadd2(hp[s2 + 1], hp[s3 + 1]));
        float2 fx = __half22float2(sx);
        float2 fy = __half22float2(sy);
        a0 += fx.x; a1 += fx.y; a2 += fy.x; a3 += fy.y;
    }
    for (; j < cnt; j++) {
        int s = g_csr[base + j] * 64 + li;
        float2 p = __half22float2(hp[s]);
        float2 q = __half22float2(hp[s + 1]);
        a0 += p.x; a1 += p.y; a2 += q.x; a3 += q.y;
    }

    float2 ps = __half22float2(hp[w * 64 + li]);
    float2 qs = __half22float2(hp[w * 64 + li + 1]);
    float dw = rsqrtf((float)(cntt + 1));
    float4 bb = ((const float4*)b1)[lane];
    float r0 = fmaxf(fmaf(dw, a0 + ps.x, bb.x), 0.f);
    float r1 = fmaxf(fmaf(dw, a1 + ps.y, bb.y), 0.f);
    float r2 = fmaxf(fmaf(dw, a2 + qs.x, bb.z), 0.f);
    float r3 = fmaxf(fmaf(dw, a3 + qs.y, bb.w), 0.f);

    __half2* op = (__half2*)&g_act1h[w * 128 + lane * 4];
    op[0] = __floats2half2_rn(r0, r1);
    op[1] = __floats2half2_rn(r2, r3);
}

// Layer-2 pull + bias + log_softmax. Warp per node, 2 cols per lane.
__global__ void agg2_kernel(const float* __restrict__ b2,
                            float* __restrict__ out, int n) {
    int w    = (blockIdx.x * blockDim.x + threadIdx.x) >> 5;
    int lane = threadIdx.x & 31;
    if (w >= n) return;

    int cntt = g_cnt[w];
    int cnt  = cntt < CAP ? cntt : CAP;
    int base = w * CAP;
    const __half2* hp = (const __half2*)g_h2h;  // half2 per lane per row

    float ax = 0.f, ay = 0.f;
    int j = 0;
    for (; j + 8 <= cnt; j += 8) {
        __half2 x0 = hp[g_csr[base + j + 0] * 32 + lane];
        __half2 x1 = hp[g_csr[base + j + 1] * 32 + lane];
        __half2 x2 = hp[g_csr[base + j + 2] * 32 + lane];
        __half2 x3 = hp[g_csr[base + j + 3] * 32 + lane];
        __half2 x4 = hp[g_csr[base + j + 4] * 32 + lane];
        __half2 x5 = hp[g_csr[base + j + 5] * 32 + lane];
        __half2 x6 = hp[g_csr[base + j + 6] * 32 + lane];
        __half2 x7 = hp[g_csr[base + j + 7] * 32 + lane];
        __half2 s = __hadd2(__hadd2(__hadd2(x0, x1), __hadd2(x2, x3)),
                            __hadd2(__hadd2(x4, x5), __hadd2(x6, x7)));
        float2 f = __half22float2(s);
        ax += f.x; ay += f.y;
    }
    for (; j + 4 <= cnt; j += 4) {
        __half2 s = __hadd2(
            __hadd2(hp[g_csr[base + j + 0] * 32 + lane],
                    hp[g_csr[base + j + 1] * 32 + lane]),
            __hadd2(hp[g_csr[base + j + 2] * 32 + lane],
                    hp[g_csr[base + j + 3] * 32 + lane]));
        float2 f = __half22float2(s);
        ax += f.x; ay += f.y;
    }
    for (; j < cnt; j++) {
        float2 f = __half22float2(hp[g_csr[base + j] * 32 + lane]);
        ax += f.x; ay += f.y;
    }

    float2 fs = __half22float2(hp[w * 32 + lane]);
    float dw = rsqrtf((float)(cntt + 1));
    float2 bb = ((const float2*)b2)[lane];
    float ox = fmaf(dw, ax + fs.x, bb.x);
    float oy = fmaf(dw, ay + fs.y, bb.y);

    float m = fmaxf(ox, oy);
#pragma unroll
    for (int o = 16; o; o >>= 1) m = fmaxf(m, __shfl_xor_sync(0xFFFFFFFFu, m, o));
    float s = __expf(ox - m) + __expf(oy - m);
#pragma unroll
    for (int o = 16; o; o >>= 1) s += __shfl_xor_sync(0xFFFFFFFFu, s, o);
    float lse = m + __logf(s);

    ((float2*)out)[w * 32 + lane] = make_float2(ox - lse, oy - lse);
}

// ---------------------------------------------------------------------------
extern "C" void kernel_launch(void* const* d_in, const int* in_sizes, int n_in,
                              void* d_out, int out_size) {
    const float* x  = (const float*)d_in[0];
    const int*   ei = (const int*)  d_in[1];
    const float* W1 = (const float*)d_in[2];
    const float* b1 = (const float*)d_in[3];
    const float* W2 = (const float*)d_in[4];
    const float* b2 = (const float*)d_in[5];
    float* out = (float*)d_out;

    const int n = in_sizes[0] / 128;
    const int e = in_sizes[1] / 2;
    const int* src = ei;
    const int* dst = ei + e;

    zero_cnt_kernel<<<(n + 255) / 256, 256>>>(n);
    fill_kernel    <<<(e + 255) / 256, 256>>>(src, dst, e);

    gemm1_kernel<<<(n + 127) / 128, 256>>>(x, W1, n);
    agg1_kernel <<<(n * 32 + 255) / 256, 256>>>(b1, n);
    gemm2_kernel<<<(n + 127) / 128, 256>>>(W2, n);
    agg2_kernel <<<(n * 32 + 255) / 256, 256>>>(b2, out, n);
}